// round 2
// baseline (speedup 1.0000x reference)
#include <cuda_runtime.h>
#include <math.h>

// Problem dims
#define BATCH 32
#define CCH   192
#define HW    4096                 // 64*64
#define NTOT  (BATCH * CCH * HW)   // 25,165,824 elements
#define N4    (NTOT / 4)           // float4 count

// Per-channel precomputed parameters (scratch: __device__ globals, no allocs)
__device__ float g_a[CCH];       // affine slope  (w3^T W2 W1 w0)
__device__ float g_d[CCH];       // affine offset
__device__ int   g_affine[CCH];  // 1 if all tanh(factor)==0 -> affine fast path
// Full processed params for generic fallback path:
// [0:3)=sp0  [3:12)=W1  [12:21)=W2  [21:24)=w3
// [24:27)=b0 [27:30)=b1 [30:33)=b2  [33]=b3
// [34:37)=tf0 [37:40)=tf1 [40:43)=tf2
__device__ float g_full[CCH][48];

__device__ __forceinline__ float softplusf(float x) {
    // stable softplus; inputs here are in (-0.5, 0.5) so this is plenty
    return fmaxf(x, 0.0f) + log1pf(expf(-fabsf(x)));
}

__device__ __forceinline__ float sigmoidf_(float x) {
    // matches XLA logistic lowering: 0.5 * tanh(x/2) + 0.5 (accurate tanhf)
    return fmaf(0.5f, tanhf(0.5f * x), 0.5f);
}

// ---------------------------------------------------------------------------
// Precompute: softplus all weights, tanh all factors, and compose the affine
// collapse per channel. 192 threads total; runs in a few microseconds.
// ---------------------------------------------------------------------------
__global__ void fp_precompute(const float* __restrict__ m0, const float* __restrict__ m1,
                              const float* __restrict__ m2, const float* __restrict__ m3,
                              const float* __restrict__ b0, const float* __restrict__ b1,
                              const float* __restrict__ b2, const float* __restrict__ b3,
                              const float* __restrict__ f0, const float* __restrict__ f1,
                              const float* __restrict__ f2) {
    int c = blockIdx.x * blockDim.x + threadIdx.x;
    if (c >= CCH) return;

    float sp0[3], W1[9], W2[9], w3[3];
    float B0[3], B1[3], B2[3];
    float tf0[3], tf1[3], tf2[3];

    #pragma unroll
    for (int i = 0; i < 3; i++) sp0[i] = softplusf(m0[c * 3 + i]);
    #pragma unroll
    for (int i = 0; i < 9; i++) W1[i] = softplusf(m1[c * 9 + i]);
    #pragma unroll
    for (int i = 0; i < 9; i++) W2[i] = softplusf(m2[c * 9 + i]);
    #pragma unroll
    for (int i = 0; i < 3; i++) w3[i] = softplusf(m3[c * 3 + i]);
    #pragma unroll
    for (int i = 0; i < 3; i++) { B0[i] = b0[c * 3 + i]; B1[i] = b1[c * 3 + i]; B2[i] = b2[c * 3 + i]; }
    float B3 = b3[c];
    #pragma unroll
    for (int i = 0; i < 3; i++) { tf0[i] = tanhf(f0[c * 3 + i]);
                                  tf1[i] = tanhf(f1[c * 3 + i]);
                                  tf2[i] = tanhf(f2[c * 3 + i]); }

    int aff = 1;
    #pragma unroll
    for (int i = 0; i < 3; i++)
        if (tf0[i] != 0.0f || tf1[i] != 0.0f || tf2[i] != 0.0f) aff = 0;

    // Affine collapse: logit(x) = a*x + d
    // v tracks coefficient of x, u tracks the constant term, per hidden unit.
    float v0[3], u0[3], v1[3], u1[3], v2[3], u2[3];
    #pragma unroll
    for (int i = 0; i < 3; i++) { v0[i] = sp0[i]; u0[i] = B0[i]; }
    #pragma unroll
    for (int o = 0; o < 3; o++) {
        v1[o] = W1[o*3+0]*v0[0] + W1[o*3+1]*v0[1] + W1[o*3+2]*v0[2];
        u1[o] = W1[o*3+0]*u0[0] + W1[o*3+1]*u0[1] + W1[o*3+2]*u0[2] + B1[o];
    }
    #pragma unroll
    for (int o = 0; o < 3; o++) {
        v2[o] = W2[o*3+0]*v1[0] + W2[o*3+1]*v1[1] + W2[o*3+2]*v1[2];
        u2[o] = W2[o*3+0]*u1[0] + W2[o*3+1]*u1[1] + W2[o*3+2]*u1[2] + B2[o];
    }
    float a = w3[0]*v2[0] + w3[1]*v2[1] + w3[2]*v2[2];
    float d = w3[0]*u2[0] + w3[1]*u2[1] + w3[2]*u2[2] + B3;

    g_a[c] = a;
    g_d[c] = d;
    g_affine[c] = aff;

    float* P = g_full[c];
    #pragma unroll
    for (int i = 0; i < 3; i++) P[0  + i] = sp0[i];
    #pragma unroll
    for (int i = 0; i < 9; i++) P[3  + i] = W1[i];
    #pragma unroll
    for (int i = 0; i < 9; i++) P[12 + i] = W2[i];
    #pragma unroll
    for (int i = 0; i < 3; i++) P[21 + i] = w3[i];
    #pragma unroll
    for (int i = 0; i < 3; i++) { P[24 + i] = B0[i]; P[27 + i] = B1[i]; P[30 + i] = B2[i]; }
    P[33] = B3;
    #pragma unroll
    for (int i = 0; i < 3; i++) { P[34 + i] = tf0[i]; P[37 + i] = tf1[i]; P[40 + i] = tf2[i]; }
}

// Generic full-MLP CDF evaluation (fallback for nonzero factors)
__device__ __forceinline__ float cdf_full(const float* __restrict__ P, float x) {
    float v[3], w[3];
    #pragma unroll
    for (int o = 0; o < 3; o++) {
        v[o] = fmaf(P[0 + o], x, P[24 + o]);
        v[o] = fmaf(P[34 + o], tanhf(v[o]), v[o]);
    }
    #pragma unroll
    for (int o = 0; o < 3; o++) {
        w[o] = P[27 + o] + P[3 + o*3 + 0]*v[0] + P[3 + o*3 + 1]*v[1] + P[3 + o*3 + 2]*v[2];
        w[o] = fmaf(P[37 + o], tanhf(w[o]), w[o]);
    }
    #pragma unroll
    for (int o = 0; o < 3; o++) {
        v[o] = P[30 + o] + P[12 + o*3 + 0]*w[0] + P[12 + o*3 + 1]*w[1] + P[12 + o*3 + 2]*w[2];
        v[o] = fmaf(P[40 + o], tanhf(v[o]), v[o]);
    }
    float s = P[33] + P[21]*v[0] + P[22]*v[1] + P[23]*v[2];
    return sigmoidf_(s);
}

// ---------------------------------------------------------------------------
// Main kernel: one float4 per thread. Block = 256 threads = 1024 elements =
// quarter of one (b,c) slice -> channel is uniform per block.
// ---------------------------------------------------------------------------
__global__ void __launch_bounds__(256)
fp_main(const float* __restrict__ z, float* __restrict__ out) {
    const int tid = threadIdx.x;
    const int c = (blockIdx.x >> 2) % CCH;         // 4 blocks per (b,c) slice
    const long n4 = (long)blockIdx.x * 256 + tid;  // float4 index

    const float a = g_a[c];
    const float d = g_d[c];
    const bool aff = (g_affine[c] != 0);

    float4 zz = reinterpret_cast<const float4*>(z)[n4];
    float4 zh, lk;

    if (aff) {
        float in[4] = {zz.x, zz.y, zz.z, zz.w};
        float oh[4], ol[4];
        #pragma unroll
        for (int i = 0; i < 4; i++) {
            float h  = rintf(in[i]);                 // round half-to-even, matches jnp.round
            float tu = fmaf(a, h + 0.5f, d);         // logit at z_hat + 0.5
            float up = sigmoidf_(tu);
            float lo = sigmoidf_(tu - a);            // logit at z_hat - 0.5 == tu - a
            oh[i] = h;
            ol[i] = fmaxf(up - lo, 1e-9f);
        }
        zh = make_float4(oh[0], oh[1], oh[2], oh[3]);
        lk = make_float4(ol[0], ol[1], ol[2], ol[3]);
    } else {
        __shared__ float P[48];
        if (tid < 48) P[tid] = g_full[c][tid];
        __syncthreads();
        float in[4] = {zz.x, zz.y, zz.z, zz.w};
        float oh[4], ol[4];
        #pragma unroll
        for (int i = 0; i < 4; i++) {
            float h  = rintf(in[i]);
            float up = cdf_full(P, h + 0.5f);
            float lo = cdf_full(P, h - 0.5f);
            oh[i] = h;
            ol[i] = fmaxf(up - lo, 1e-9f);
        }
        zh = make_float4(oh[0], oh[1], oh[2], oh[3]);
        lk = make_float4(ol[0], ol[1], ol[2], ol[3]);
    }

    reinterpret_cast<float4*>(out)[n4]      = zh;   // z_hat first
    reinterpret_cast<float4*>(out)[n4 + N4] = lk;   // likelihoods second
}

extern "C" void kernel_launch(void* const* d_in, const int* in_sizes, int n_in,
                              void* d_out, int out_size) {
    const float* z  = (const float*)d_in[0];
    const float* m0 = (const float*)d_in[1];
    const float* m1 = (const float*)d_in[2];
    const float* m2 = (const float*)d_in[3];
    const float* m3 = (const float*)d_in[4];
    const float* b0 = (const float*)d_in[5];
    const float* b1 = (const float*)d_in[6];
    const float* b2 = (const float*)d_in[7];
    const float* b3 = (const float*)d_in[8];
    const float* f0 = (const float*)d_in[9];
    const float* f1 = (const float*)d_in[10];
    const float* f2 = (const float*)d_in[11];

    fp_precompute<<<1, CCH>>>(m0, m1, m2, m3, b0, b1, b2, b3, f0, f1, f2);

    const int nblocks = N4 / 256;  // 24576
    fp_main<<<nblocks, 256>>>(z, (float*)d_out);
}

// round 3
// speedup vs baseline: 1.1359x; 1.1359x over previous
#include <cuda_runtime.h>
#include <math.h>

// Problem dims
#define BATCH 32
#define CCH   192
#define HW    4096                 // 64*64
#define NTOT  (BATCH * CCH * HW)   // 25,165,824 elements
#define N4    (NTOT / 4)           // float4 count

// Per-channel precomputed parameters (scratch: __device__ globals, no allocs)
__device__ float g_a[CCH];       // affine slope  (w3^T W2 W1 w0)
__device__ float g_d[CCH];       // affine offset
__device__ float g_ea[CCH];      // exp(a)
__device__ int   g_affine[CCH];  // 1 if all tanh(factor)==0 -> affine fast path
// Full processed params for generic fallback path:
// [0:3)=sp0  [3:12)=W1  [12:21)=W2  [21:24)=w3
// [24:27)=b0 [27:30)=b1 [30:33)=b2  [33]=b3
// [34:37)=tf0 [37:40)=tf1 [40:43)=tf2
__device__ float g_full[CCH][48];

__device__ __forceinline__ float softplusf(float x) {
    return fmaxf(x, 0.0f) + log1pf(expf(-fabsf(x)));
}

__device__ __forceinline__ float sigmoid_acc(float x) {
    // accurate path (fallback only)
    return fmaf(0.5f, tanhf(0.5f * x), 0.5f);
}

// ---------------------------------------------------------------------------
// Precompute: softplus weights, tanh factors, affine collapse. 192 threads.
// ---------------------------------------------------------------------------
__global__ void fp_precompute(const float* __restrict__ m0, const float* __restrict__ m1,
                              const float* __restrict__ m2, const float* __restrict__ m3,
                              const float* __restrict__ b0, const float* __restrict__ b1,
                              const float* __restrict__ b2, const float* __restrict__ b3,
                              const float* __restrict__ f0, const float* __restrict__ f1,
                              const float* __restrict__ f2) {
    int c = blockIdx.x * blockDim.x + threadIdx.x;
    if (c >= CCH) return;

    float sp0[3], W1[9], W2[9], w3[3];
    float B0[3], B1[3], B2[3];
    float tf0[3], tf1[3], tf2[3];

    #pragma unroll
    for (int i = 0; i < 3; i++) sp0[i] = softplusf(m0[c * 3 + i]);
    #pragma unroll
    for (int i = 0; i < 9; i++) W1[i] = softplusf(m1[c * 9 + i]);
    #pragma unroll
    for (int i = 0; i < 9; i++) W2[i] = softplusf(m2[c * 9 + i]);
    #pragma unroll
    for (int i = 0; i < 3; i++) w3[i] = softplusf(m3[c * 3 + i]);
    #pragma unroll
    for (int i = 0; i < 3; i++) { B0[i] = b0[c * 3 + i]; B1[i] = b1[c * 3 + i]; B2[i] = b2[c * 3 + i]; }
    float B3 = b3[c];
    #pragma unroll
    for (int i = 0; i < 3; i++) { tf0[i] = tanhf(f0[c * 3 + i]);
                                  tf1[i] = tanhf(f1[c * 3 + i]);
                                  tf2[i] = tanhf(f2[c * 3 + i]); }

    int aff = 1;
    #pragma unroll
    for (int i = 0; i < 3; i++)
        if (tf0[i] != 0.0f || tf1[i] != 0.0f || tf2[i] != 0.0f) aff = 0;

    // Affine collapse: logit(x) = a*x + d
    float v0[3], u0[3], v1[3], u1[3], v2[3], u2[3];
    #pragma unroll
    for (int i = 0; i < 3; i++) { v0[i] = sp0[i]; u0[i] = B0[i]; }
    #pragma unroll
    for (int o = 0; o < 3; o++) {
        v1[o] = W1[o*3+0]*v0[0] + W1[o*3+1]*v0[1] + W1[o*3+2]*v0[2];
        u1[o] = W1[o*3+0]*u0[0] + W1[o*3+1]*u0[1] + W1[o*3+2]*u0[2] + B1[o];
    }
    #pragma unroll
    for (int o = 0; o < 3; o++) {
        v2[o] = W2[o*3+0]*v1[0] + W2[o*3+1]*v1[1] + W2[o*3+2]*v1[2];
        u2[o] = W2[o*3+0]*u1[0] + W2[o*3+1]*u1[1] + W2[o*3+2]*u1[2] + B2[o];
    }
    float a = w3[0]*v2[0] + w3[1]*v2[1] + w3[2]*v2[2];
    float d = w3[0]*u2[0] + w3[1]*u2[1] + w3[2]*u2[2] + B3;

    g_a[c] = a;
    g_d[c] = d;
    g_ea[c] = expf(a);
    g_affine[c] = aff;

    float* P = g_full[c];
    #pragma unroll
    for (int i = 0; i < 3; i++) P[0  + i] = sp0[i];
    #pragma unroll
    for (int i = 0; i < 9; i++) P[3  + i] = W1[i];
    #pragma unroll
    for (int i = 0; i < 9; i++) P[12 + i] = W2[i];
    #pragma unroll
    for (int i = 0; i < 3; i++) P[21 + i] = w3[i];
    #pragma unroll
    for (int i = 0; i < 3; i++) { P[24 + i] = B0[i]; P[27 + i] = B1[i]; P[30 + i] = B2[i]; }
    P[33] = B3;
    #pragma unroll
    for (int i = 0; i < 3; i++) { P[34 + i] = tf0[i]; P[37 + i] = tf1[i]; P[40 + i] = tf2[i]; }
}

// Generic full-MLP CDF evaluation (fallback for nonzero factors)
__device__ float cdf_full(const float* __restrict__ P, float x) {
    float v[3], w[3];
    #pragma unroll
    for (int o = 0; o < 3; o++) {
        v[o] = fmaf(P[0 + o], x, P[24 + o]);
        v[o] = fmaf(P[34 + o], tanhf(v[o]), v[o]);
    }
    #pragma unroll
    for (int o = 0; o < 3; o++) {
        w[o] = P[27 + o] + P[3 + o*3 + 0]*v[0] + P[3 + o*3 + 1]*v[1] + P[3 + o*3 + 2]*v[2];
        w[o] = fmaf(P[37 + o], tanhf(w[o]), w[o]);
    }
    #pragma unroll
    for (int o = 0; o < 3; o++) {
        v[o] = P[30 + o] + P[12 + o*3 + 0]*w[0] + P[12 + o*3 + 1]*w[1] + P[12 + o*3 + 2]*w[2];
        v[o] = fmaf(P[40 + o], tanhf(v[o]), v[o]);
    }
    float s = P[33] + P[21]*v[0] + P[22]*v[1] + P[23]*v[2];
    return sigmoid_acc(s);
}

// Cold path extracted so its register appetite doesn't inflate the hot path.
__device__ __noinline__ void fp_fallback(int c, int tid, const float4 zz,
                                         float4* zh_out, float4* lk_out) {
    __shared__ float P[48];
    if (tid < 48) P[tid] = g_full[c][tid];
    __syncthreads();
    float in[4] = {zz.x, zz.y, zz.z, zz.w};
    float oh[4], ol[4];
    #pragma unroll
    for (int i = 0; i < 4; i++) {
        float h  = rintf(in[i]);
        float up = cdf_full(P, h + 0.5f);
        float lo = cdf_full(P, h - 0.5f);
        oh[i] = h;
        ol[i] = fmaxf(up - lo, 1e-9f);
    }
    *zh_out = make_float4(oh[0], oh[1], oh[2], oh[3]);
    *lk_out = make_float4(ol[0], ol[1], ol[2], ol[3]);
}

// ---------------------------------------------------------------------------
// Main kernel: one float4 per thread. 4 blocks per (b,c) slice -> channel is
// uniform per block.
// Affine path per element:
//   t   = a*(zh+0.5)+d
//   e1  = exp(-t);  e2 = e1*exp(a)            (lower logit = t - a)
//   up  = 1/(1+e1); lo = 1/(1+e2)
//   lik = max(up-lo, 1e-9)
// Tails: e -> 0 or inf give up==lo exactly -> clip, same as fp32 reference.
// ---------------------------------------------------------------------------
__global__ void __launch_bounds__(256, 8)
fp_main(const float* __restrict__ z, float* __restrict__ out) {
    const int tid = threadIdx.x;
    const int c = (blockIdx.x >> 2) % CCH;         // 4 blocks per (b,c) slice
    const long n4 = (long)blockIdx.x * 256 + tid;  // float4 index

    const float a  = g_a[c];
    const float d  = g_d[c];
    const float ea = g_ea[c];

    float4 zz = reinterpret_cast<const float4*>(z)[n4];
    float4 zh, lk;

    if (g_affine[c] != 0) {
        float in[4] = {zz.x, zz.y, zz.z, zz.w};
        float oh[4], ol[4];
        #pragma unroll
        for (int i = 0; i < 4; i++) {
            float h  = rintf(in[i]);                 // half-to-even, matches jnp.round
            float t  = fmaf(a, h + 0.5f, d);
            float e1 = __expf(-t);
            float e2 = e1 * ea;
            float up = __frcp_rn(1.0f + e1);
            float lo = __frcp_rn(1.0f + e2);
            oh[i] = h;
            ol[i] = fmaxf(up - lo, 1e-9f);
        }
        zh = make_float4(oh[0], oh[1], oh[2], oh[3]);
        lk = make_float4(ol[0], ol[1], ol[2], ol[3]);
    } else {
        fp_fallback(c, tid, zz, &zh, &lk);
    }

    reinterpret_cast<float4*>(out)[n4]      = zh;   // z_hat first
    reinterpret_cast<float4*>(out)[n4 + N4] = lk;   // likelihoods second
}

extern "C" void kernel_launch(void* const* d_in, const int* in_sizes, int n_in,
                              void* d_out, int out_size) {
    const float* z  = (const float*)d_in[0];
    const float* m0 = (const float*)d_in[1];
    const float* m1 = (const float*)d_in[2];
    const float* m2 = (const float*)d_in[3];
    const float* m3 = (const float*)d_in[4];
    const float* b0 = (const float*)d_in[5];
    const float* b1 = (const float*)d_in[6];
    const float* b2 = (const float*)d_in[7];
    const float* b3 = (const float*)d_in[8];
    const float* f0 = (const float*)d_in[9];
    const float* f1 = (const float*)d_in[10];
    const float* f2 = (const float*)d_in[11];

    fp_precompute<<<1, CCH>>>(m0, m1, m2, m3, b0, b1, b2, b3, f0, f1, f2);

    const int nblocks = N4 / 256;  // 24576
    fp_main<<<nblocks, 256>>>(z, (float*)d_out);
}

// round 4
// speedup vs baseline: 1.2417x; 1.0931x over previous
#include <cuda_runtime.h>
#include <math.h>

// Problem dims
#define BATCH 32
#define CCH   192
#define HW    4096                 // 64*64
#define NTOT  (BATCH * CCH * HW)   // 25,165,824 elements
#define N4    (NTOT / 4)           // float4 count
#define LOG2E 1.4426950408889634f

// Per-channel precomputed parameters (scratch: __device__ globals, no allocs)
__device__ float g_na[CCH];      // -a * log2e
__device__ float g_nd[CCH];      // -(0.5a + d) * log2e
__device__ float g_ea[CCH];      // exp(a)
__device__ int   g_affine[CCH];  // 1 if all tanh(factor)==0 -> affine fast path
// Full processed params for generic fallback path:
// [0:3)=sp0  [3:12)=W1  [12:21)=W2  [21:24)=w3
// [24:27)=b0 [27:30)=b1 [30:33)=b2  [33]=b3
// [34:37)=tf0 [37:40)=tf1 [40:43)=tf2
__device__ float g_full[CCH][48];

__device__ __forceinline__ float softplus_fast(float x) {
    // |x| < 0.5 here; fast intrinsics are plenty accurate vs 1e-3 tolerance
    return fmaxf(x, 0.0f) + __logf(1.0f + __expf(-fabsf(x)));
}

__device__ __forceinline__ float sigmoid_acc(float x) {
    return fmaf(0.5f, tanhf(0.5f * x), 0.5f);
}

__device__ __forceinline__ float ex2_approx(float x) {
    float r; asm("ex2.approx.f32 %0, %1;" : "=f"(r) : "f"(x)); return r;
}
__device__ __forceinline__ float rcp_approx(float x) {
    float r; asm("rcp.approx.f32 %0, %1;" : "=f"(r) : "f"(x)); return r;
}

// ---------------------------------------------------------------------------
// Precompute: softplus weights, tanh factors, affine collapse. 192 threads.
// ---------------------------------------------------------------------------
__global__ void fp_precompute(const float* __restrict__ m0, const float* __restrict__ m1,
                              const float* __restrict__ m2, const float* __restrict__ m3,
                              const float* __restrict__ b0, const float* __restrict__ b1,
                              const float* __restrict__ b2, const float* __restrict__ b3,
                              const float* __restrict__ f0, const float* __restrict__ f1,
                              const float* __restrict__ f2) {
    int c = blockIdx.x * blockDim.x + threadIdx.x;
    if (c >= CCH) return;

    float sp0[3], W1[9], W2[9], w3[3];
    float B0[3], B1[3], B2[3];
    float tf0[3], tf1[3], tf2[3];

    #pragma unroll
    for (int i = 0; i < 3; i++) sp0[i] = softplus_fast(m0[c * 3 + i]);
    #pragma unroll
    for (int i = 0; i < 9; i++) W1[i] = softplus_fast(m1[c * 9 + i]);
    #pragma unroll
    for (int i = 0; i < 9; i++) W2[i] = softplus_fast(m2[c * 9 + i]);
    #pragma unroll
    for (int i = 0; i < 3; i++) w3[i] = softplus_fast(m3[c * 3 + i]);
    #pragma unroll
    for (int i = 0; i < 3; i++) { B0[i] = b0[c * 3 + i]; B1[i] = b1[c * 3 + i]; B2[i] = b2[c * 3 + i]; }
    float B3 = b3[c];
    #pragma unroll
    for (int i = 0; i < 3; i++) { tf0[i] = tanhf(f0[c * 3 + i]);
                                  tf1[i] = tanhf(f1[c * 3 + i]);
                                  tf2[i] = tanhf(f2[c * 3 + i]); }

    int aff = 1;
    #pragma unroll
    for (int i = 0; i < 3; i++)
        if (tf0[i] != 0.0f || tf1[i] != 0.0f || tf2[i] != 0.0f) aff = 0;

    // Affine collapse: logit(x) = a*x + d
    float v0[3], u0[3], v1[3], u1[3], v2[3], u2[3];
    #pragma unroll
    for (int i = 0; i < 3; i++) { v0[i] = sp0[i]; u0[i] = B0[i]; }
    #pragma unroll
    for (int o = 0; o < 3; o++) {
        v1[o] = W1[o*3+0]*v0[0] + W1[o*3+1]*v0[1] + W1[o*3+2]*v0[2];
        u1[o] = W1[o*3+0]*u0[0] + W1[o*3+1]*u0[1] + W1[o*3+2]*u0[2] + B1[o];
    }
    #pragma unroll
    for (int o = 0; o < 3; o++) {
        v2[o] = W2[o*3+0]*v1[0] + W2[o*3+1]*v1[1] + W2[o*3+2]*v1[2];
        u2[o] = W2[o*3+0]*u1[0] + W2[o*3+1]*u1[1] + W2[o*3+2]*u1[2] + B2[o];
    }
    float a = w3[0]*v2[0] + w3[1]*v2[1] + w3[2]*v2[2];
    float d = w3[0]*u2[0] + w3[1]*u2[1] + w3[2]*u2[2] + B3;

    g_na[c] = -a * LOG2E;
    g_nd[c] = -(0.5f * a + d) * LOG2E;
    g_ea[c] = __expf(a);
    g_affine[c] = aff;

    float* P = g_full[c];
    #pragma unroll
    for (int i = 0; i < 3; i++) P[0  + i] = sp0[i];
    #pragma unroll
    for (int i = 0; i < 9; i++) P[3  + i] = W1[i];
    #pragma unroll
    for (int i = 0; i < 9; i++) P[12 + i] = W2[i];
    #pragma unroll
    for (int i = 0; i < 3; i++) P[21 + i] = w3[i];
    #pragma unroll
    for (int i = 0; i < 3; i++) { P[24 + i] = B0[i]; P[27 + i] = B1[i]; P[30 + i] = B2[i]; }
    P[33] = B3;
    #pragma unroll
    for (int i = 0; i < 3; i++) { P[34 + i] = tf0[i]; P[37 + i] = tf1[i]; P[40 + i] = tf2[i]; }
}

// Generic full-MLP CDF evaluation (fallback for nonzero factors)
__device__ float cdf_full(const float* __restrict__ P, float x) {
    float v[3], w[3];
    #pragma unroll
    for (int o = 0; o < 3; o++) {
        v[o] = fmaf(P[0 + o], x, P[24 + o]);
        v[o] = fmaf(P[34 + o], tanhf(v[o]), v[o]);
    }
    #pragma unroll
    for (int o = 0; o < 3; o++) {
        w[o] = P[27 + o] + P[3 + o*3 + 0]*v[0] + P[3 + o*3 + 1]*v[1] + P[3 + o*3 + 2]*v[2];
        w[o] = fmaf(P[37 + o], tanhf(w[o]), w[o]);
    }
    #pragma unroll
    for (int o = 0; o < 3; o++) {
        v[o] = P[30 + o] + P[12 + o*3 + 0]*w[0] + P[12 + o*3 + 1]*w[1] + P[12 + o*3 + 2]*w[2];
        v[o] = fmaf(P[40 + o], tanhf(v[o]), v[o]);
    }
    float s = P[33] + P[21]*v[0] + P[22]*v[1] + P[23]*v[2];
    return sigmoid_acc(s);
}

// Cold path, kept out of the hot path's register budget.
__device__ __noinline__ void fp_fallback(int c, int tid, const float4 zz,
                                         float4* zh_out, float4* lk_out) {
    __shared__ float P[48];
    if (tid < 48) P[tid] = g_full[c][tid];
    __syncthreads();
    float in[4] = {zz.x, zz.y, zz.z, zz.w};
    float oh[4], ol[4];
    #pragma unroll
    for (int i = 0; i < 4; i++) {
        float h  = rintf(in[i]);
        float up = cdf_full(P, h + 0.5f);
        float lo = cdf_full(P, h - 0.5f);
        oh[i] = h;
        ol[i] = fmaxf(up - lo, 1e-9f);
    }
    *zh_out = make_float4(oh[0], oh[1], oh[2], oh[3]);
    *lk_out = make_float4(ol[0], ol[1], ol[2], ol[3]);
}

// ---------------------------------------------------------------------------
// Main kernel: 8 elements (2 float4, stride 256) per thread.
// Block covers 2048 elements = half a (b,c) slice -> channel uniform.
// Per element (affine path):
//   h   = rint(z)
//   e1  = 2^(na*h + nd)          == exp(-(a*(h+0.5)+d))
//   e2  = e1 * exp(a)            == exp(-(t - a))
//   lik = max((e2-e1) * rcp((1+e1)*(1+e2)), 1e-9)
// Tails: e1 -> inf gives num = NaN; fmaxf(NaN,1e-9)=1e-9 = clipped 0 (matches ref).
//        e1 -> 0 gives num = 0 -> 1e-9 (matches ref).
// ---------------------------------------------------------------------------
__global__ void __launch_bounds__(256)
fp_main(const float* __restrict__ z, float* __restrict__ out) {
    const int tid = threadIdx.x;
    const int c = (blockIdx.x >> 1) % CCH;          // 2 blocks per (b,c) slice
    const long n4 = (long)blockIdx.x * 512 + tid;   // first float4 index

    const float na = g_na[c];
    const float nd = g_nd[c];
    const float ea = g_ea[c];

    const float4* zin = reinterpret_cast<const float4*>(z);
    float4* o = reinterpret_cast<float4*>(out);

    float4 zz0 = zin[n4];
    float4 zz1 = zin[n4 + 256];

    if (g_affine[c] != 0) {
        float in[8] = {zz0.x, zz0.y, zz0.z, zz0.w, zz1.x, zz1.y, zz1.z, zz1.w};
        float oh[8], ol[8];
        #pragma unroll
        for (int i = 0; i < 8; i++) {
            float h   = rintf(in[i]);                 // half-to-even, matches jnp.round
            float e1  = ex2_approx(fmaf(na, h, nd));
            float e2  = e1 * ea;
            float num = e2 - e1;
            float den = (1.0f + e1) * (1.0f + e2);
            oh[i] = h;
            ol[i] = fmaxf(num * rcp_approx(den), 1e-9f);
        }
        o[n4]             = make_float4(oh[0], oh[1], oh[2], oh[3]);
        o[n4 + 256]       = make_float4(oh[4], oh[5], oh[6], oh[7]);
        o[n4 + N4]        = make_float4(ol[0], ol[1], ol[2], ol[3]);
        o[n4 + N4 + 256]  = make_float4(ol[4], ol[5], ol[6], ol[7]);
    } else {
        float4 zh0, lk0, zh1, lk1;
        fp_fallback(c, tid, zz0, &zh0, &lk0);
        fp_fallback(c, tid, zz1, &zh1, &lk1);
        o[n4]            = zh0;
        o[n4 + 256]      = zh1;
        o[n4 + N4]       = lk0;
        o[n4 + N4 + 256] = lk1;
    }
}

extern "C" void kernel_launch(void* const* d_in, const int* in_sizes, int n_in,
                              void* d_out, int out_size) {
    const float* z  = (const float*)d_in[0];
    const float* m0 = (const float*)d_in[1];
    const float* m1 = (const float*)d_in[2];
    const float* m2 = (const float*)d_in[3];
    const float* m3 = (const float*)d_in[4];
    const float* b0 = (const float*)d_in[5];
    const float* b1 = (const float*)d_in[6];
    const float* b2 = (const float*)d_in[7];
    const float* b3 = (const float*)d_in[8];
    const float* f0 = (const float*)d_in[9];
    const float* f1 = (const float*)d_in[10];
    const float* f2 = (const float*)d_in[11];

    fp_precompute<<<1, CCH>>>(m0, m1, m2, m3, b0, b1, b2, b3, f0, f1, f2);

    const int nblocks = N4 / 512;  // 12288
    fp_main<<<nblocks, 256>>>(z, (float*)d_out);
}